// round 16
// baseline (speedup 1.0000x reference)
#include <cuda_runtime.h>
#include <cuda_bf16.h>
#include <cstdint>

// CRF log-likelihood, B=128, L=1024, T=128.
// R16 = R14 work arrangement flipped from ILP to TLP:
//   fwd/bwd split (EXACT: Z_b = alpha_511 . beta_512). 128 CTAs x 256 thr:
//   CTA c<64 runs fwd chains of batches (c, c+64); c>=64 bwd chains of
//   (c-64, c). Threads 0-127 = chain A, 128-255 = chain B, so each SMSP
//   hosts one A-warp and one B-warp -> mutual latency hiding across the
//   shared per-superstep barrier. Each thread runs the R13 single-chain
//   body: E column/row in 64 packed bf16x2 regs, 16 LDS.128 + 64 HFMA2,
//   8 accumulators, f32 tail. Exact pow-2 renorm every 4 steps.
//   Numerator + tags in the per-batch combine kernel.

#define BB 128
#define LL 1024
#define TT 128
#define HALF 512
#define LN2 0.69314718055994530942

__device__ float g_alpha[BB][TT];
__device__ float g_beta[BB][TT];
__device__ float g_mx0[BB];
__device__ int g_kf[BB];
__device__ int g_kb[BB];
__device__ double g_logl[BB];

__device__ __forceinline__ __nv_bfloat162 bc2(unsigned v) {
    return *reinterpret_cast<const __nv_bfloat162 *>(&v);
}

// Single-chain bf16 matvec: 16 LDS.128 + 64 HFMA2, 8 accumulators.
__device__ __forceinline__ float matvec_bf16(const uint4 *u4,
                                             const __nv_bfloat162 *Ec) {
    const __nv_bfloat162 z = __floats2bfloat162_rn(0.f, 0.f);
    __nv_bfloat162 a[8] = {z, z, z, z, z, z, z, z};
#pragma unroll
    for (int q = 0; q < 16; q++) {
        uint4 U = u4[q];
        const __nv_bfloat162 *e = Ec + 4 * q;
        const int p = (q & 1) * 4;
        a[p + 0] = __hfma2(bc2(U.x), e[0], a[p + 0]);
        a[p + 1] = __hfma2(bc2(U.y), e[1], a[p + 1]);
        a[p + 2] = __hfma2(bc2(U.z), e[2], a[p + 2]);
        a[p + 3] = __hfma2(bc2(U.w), e[3], a[p + 3]);
    }
    __nv_bfloat162 t0 = __hadd2(__hadd2(a[0], a[4]), __hadd2(a[1], a[5]));
    __nv_bfloat162 t1 = __hadd2(__hadd2(a[2], a[6]), __hadd2(a[3], a[7]));
    __nv_bfloat162 s = __hadd2(t0, t1);
    return __low2float(s) + __high2float(s);
}

__global__ __launch_bounds__(256, 1) void crf_main(
    const float *__restrict__ inputs,       // [B, L, T]
    const float *__restrict__ trans,        // [T, T]
    const float *__restrict__ start_t,      // [T]
    const float *__restrict__ end_t)        // [T]
{
    const int tid = threadIdx.x;
    const int lane = tid & 31;
    const int wid = tid >> 5;          // 0..7
    const int g = tid >> 7;            // chain group: 0 = A, 1 = B
    const int t = tid & 127;           // position within chain
    const int rw = wid & 3;            // warp index within group
    const int c = blockIdx.x;
    const int fwd = (c < 64);
    const int b = (fwd ? c : c - 64) + g * 64;

    const float *eG = inputs + (size_t)b * (LL * TT);

    __shared__ __align__(16) __nv_bfloat16 u_sh[2][2][TT];  // [group][buf][t]
    __shared__ __align__(16) unsigned red_u[2][4];
    __shared__ float red_f[8];

    __nv_bfloat162 Ec[64];       // packed E column (fwd) / row (bwd)
    float em[4];                 // emission LDG register ring (4 ahead)
    int ksum = 0;
    float un;

    // ---- E into registers (identical for both groups; same direction) -----
    if (fwd) {
#pragma unroll
        for (int q = 0; q < 64; q++) {
            float lo = __expf(trans[(2 * q) * TT + t]);
            float hi = __expf(trans[(2 * q + 1) * TT + t]);
            Ec[q] = __floats2bfloat162_rn(lo, hi);
        }
    } else {
        const float2 *trow = (const float2 *)(trans + t * TT);
#pragma unroll
        for (int q = 0; q < 64; q++) {
            float2 tv = trow[q];
            Ec[q] = __floats2bfloat162_rn(__expf(tv.x), __expf(tv.y));
        }
    }

    if (fwd) {
        // ========== FORWARD: a_0 .. a_511 for this group's batch ===========
        float a0 = start_t[t] + eG[t];
        float mv = a0;
#pragma unroll
        for (int o = 16; o; o >>= 1)
            mv = fmaxf(mv, __shfl_xor_sync(0xffffffffu, mv, o));
        if (lane == 0) red_f[wid] = mv;
        __syncthreads();
        const float mx0 = fmaxf(fmaxf(red_f[4 * g + 0], red_f[4 * g + 1]),
                                fmaxf(red_f[4 * g + 2], red_f[4 * g + 3]));
        un = __expf(a0 - mx0);            // u_0, max == 1
        u_sh[g][0][t] = __float2bfloat16(un);
        {
            unsigned wm = __reduce_max_sync(0xffffffffu, __float_as_uint(un));
            if (lane == 0) red_u[g][rw] = wm;
        }
        if (t == 0) g_mx0[b] = mx0;
#pragma unroll
        for (int i = 0; i < 4; i++) em[i] = eG[(1 + i) * TT + t];
        __syncthreads();

        // 511 steps; step s consumes emission row s+1
        auto fwd_step = [&](int s, int j) {
            float m = __expf(em[j]);
            int nrow = s + 5; if (nrow > HALF - 1) nrow = HALF - 1;
            const float enew = eG[nrow * TT + t];
            if ((s & 3) == 0) {           // apply exact pow-2 scale
                uint4 r4 = *(const uint4 *)red_u[g];
                unsigned mb = max(max(r4.x, r4.y), max(r4.z, r4.w));
                int k = (int)(mb >> 23) - 127;
                ksum += k;
                m *= __uint_as_float((unsigned)(127 - k) << 23);
            }
            un = matvec_bf16(
                reinterpret_cast<const uint4 *>(u_sh[g][s & 1]), Ec) * m;
            em[j] = enew;
            u_sh[g][(s + 1) & 1][t] = __float2bfloat16(un);
            if ((s & 3) == 3) {
                unsigned w = __reduce_max_sync(0xffffffffu, __float_as_uint(un));
                if (lane == 0) red_u[g][rw] = w;
            }
            __syncthreads();
        };
#pragma unroll 1
        for (int blk = 0; blk < 127; ++blk) {
#pragma unroll
            for (int sub = 0; sub < 4; ++sub)
                fwd_step(blk * 4 + sub, sub);
        }
        fwd_step(508, 0); fwd_step(509, 1); fwd_step(510, 2);

        g_alpha[b][t] = un;
        if (t == 0) g_kf[b] = ksum;
    } else {
        // ========== BACKWARD: beta_1024 -> beta_512 for this batch =========
        un = __expf(end_t[t]);
        {
            unsigned wm = __reduce_max_sync(0xffffffffu, __float_as_uint(un));
            if (lane == 0) red_u[g][rw] = wm;
        }
#pragma unroll
        for (int i = 0; i < 4; i++) em[i] = eG[(1023 - i) * TT + t];
        __syncthreads();

        // 512 steps; step s consumes emission row 1023-s.
        // renorm: capture post-matvec at s%4==3, apply at s%4==1.
        auto bwd_step = [&](int s, int j) {
            float m = __expf(em[j]);
            float v = un * m;
            if ((s & 3) == 1) {
                uint4 r4 = *(const uint4 *)red_u[g];
                unsigned mb = max(max(r4.x, r4.y), max(r4.z, r4.w));
                int k = (int)(mb >> 23) - 127;
                ksum += k;
                v *= __uint_as_float((unsigned)(127 - k) << 23);
            }
            u_sh[g][s & 1][t] = __float2bfloat16(v);
            __syncthreads();              // v published
            // post-barrier window: independent prefetch before dependent LDS
            int nrow = 1023 - s - 4; if (nrow < HALF) nrow = HALF;
            em[j] = eG[nrow * TT + t];
            un = matvec_bf16(
                reinterpret_cast<const uint4 *>(u_sh[g][s & 1]), Ec);
            if ((s & 3) == 3) {
                unsigned w = __reduce_max_sync(0xffffffffu, __float_as_uint(un));
                if (lane == 0) red_u[g][rw] = w;
            }
        };
#pragma unroll 1
        for (int blk = 0; blk < 128; ++blk) {
#pragma unroll
            for (int sub = 0; sub < 4; ++sub)
                bwd_step(blk * 4 + sub, sub);
        }

        g_beta[b][t] = un;
        if (t == 0) g_kb[b] = ksum;
    }
}

// Per-batch: numerator gathers + alpha.beta dot + logs -> g_logl[b]
__global__ __launch_bounds__(128) void crf_combine(
    const float *__restrict__ inputs,
    const void *__restrict__ tags_raw,
    const float *__restrict__ trans,
    const float *__restrict__ start_t,
    const float *__restrict__ end_t)
{
    const int b = blockIdx.x;
    const int tid = threadIdx.x;
    const int lane = tid & 31;
    const int wid = tid >> 5;
    __shared__ float rf[8];

    const float *emitB = inputs + (size_t)b * (LL * TT);

    // tags dtype detection: probe batch-0 odd int32 words (always in-bounds).
    const int *t32 = (const int *)tags_raw;
    const int is64 = !__syncthreads_or(t32[2 * tid + 1] != 0);
    const long long *t64 = (const long long *)tags_raw;
    const long tb = (long)b * LL;
    auto tg = [&](int t) -> int {
        return is64 ? (int)t64[tb + t] : t32[tb + t];
    };

    // numerator
    float np = 0.f;
#pragma unroll
    for (int k = 0; k < 8; k++) {
        int t = tid + 128 * k;
        int g = tg(t);
        np += emitB[t * TT + g];
        if (t < LL - 1) np += trans[g * TT + tg(t + 1)];
    }
    if (tid == 0) np += start_t[tg(0)] + end_t[tg(LL - 1)];

    // alpha . beta
    float p = g_alpha[b][tid] * g_beta[b][tid];

#pragma unroll
    for (int o = 16; o; o >>= 1) {
        np += __shfl_xor_sync(0xffffffffu, np, o);
        p  += __shfl_xor_sync(0xffffffffu, p, o);
    }
    if (lane == 0) { rf[wid] = np; rf[4 + wid] = p; }
    __syncthreads();
    if (tid == 0) {
        float num = rf[0] + rf[1] + rf[2] + rf[3];
        float S = rf[4] + rf[5] + rf[6] + rf[7];
        double logZ = (double)g_mx0[b] +
                      (double)(g_kf[b] + g_kb[b]) * LN2 + log((double)S);
        g_logl[b] = (double)num - logZ;
    }
}

__global__ __launch_bounds__(128) void crf_finish(float *__restrict__ out) {
    const int t = threadIdx.x;
    const int lane = t & 31;
    const int wid = t >> 5;
    __shared__ double rd[4];

    double v = g_logl[t];
#pragma unroll
    for (int o = 16; o; o >>= 1) v += __shfl_xor_sync(0xffffffffu, v, o);
    if (lane == 0) rd[wid] = v;
    __syncthreads();
    if (t == 0) out[0] = (float)(rd[0] + rd[1] + rd[2] + rd[3]);
}

extern "C" void kernel_launch(void *const *d_in, const int *in_sizes, int n_in,
                              void *d_out, int out_size) {
    const float *inputs    = (const float *)d_in[0];
    const void  *tags      = (const void *)d_in[1];
    // d_in[2] = mask (all ones by construction) — unused
    const float *trans     = (const float *)d_in[3];
    const float *start_t   = (const float *)d_in[4];
    const float *end_t     = (const float *)d_in[5];
    float *out = (float *)d_out;

    crf_main<<<BB, 256>>>(inputs, trans, start_t, end_t);
    crf_combine<<<BB, 128>>>(inputs, tags, trans, start_t, end_t);
    crf_finish<<<1, 128>>>(out);
}

// round 17
// speedup vs baseline: 1.7801x; 1.7801x over previous
#include <cuda_runtime.h>
#include <cuda_bf16.h>
#include <cstdint>

// CRF log-likelihood, B=128, L=1024, T=128.
// R17 = R14 (champion: fwd/bwd split, Z_b = alpha_511 . beta_512 EXACT;
// 128 CTAs x 128 thr; 2 same-direction chains per CTA sharing ONE bf16
// E-register set; dual matvec interleaved IN-THREAD (ILP); one barrier per
// superstep) + overhead shave:
//   - exact pow-2 renorm every 8 steps (was 4; growth <= 2^110 << bf16 range)
//   - emission ring depth 8, step loop unrolled x8
//   - finish kernel dropped: main zeroes out, combine atomicAdds.

#define BB 128
#define LL 1024
#define TT 128
#define HALF 512
#define LN2 0.69314718055994530942

__device__ float g_alpha[BB][TT];
__device__ float g_beta[BB][TT];
__device__ float g_mx0[BB];
__device__ int g_kf[BB];
__device__ int g_kb[BB];

__device__ __forceinline__ __nv_bfloat162 bc2(unsigned v) {
    return *reinterpret_cast<const __nv_bfloat162 *>(&v);
}

// Dual bf16 matvec: both chains against the SAME Ec registers, interleaved
// in one instruction stream. Per chain: 16 LDS.128 + 64 HFMA2, 4 accs.
__device__ __forceinline__ void matvec_bf16_dual(
    const uint4 *uA4, const uint4 *uB4, const __nv_bfloat162 *Ec,
    float &outA, float &outB)
{
    const __nv_bfloat162 z = __floats2bfloat162_rn(0.f, 0.f);
    __nv_bfloat162 a0 = z, a1 = z, a2 = z, a3 = z;
    __nv_bfloat162 b0 = z, b1 = z, b2 = z, b3 = z;
#pragma unroll
    for (int q = 0; q < 16; q++) {
        uint4 UA = uA4[q];
        uint4 UB = uB4[q];
        const __nv_bfloat162 *e = Ec + 4 * q;
        a0 = __hfma2(bc2(UA.x), e[0], a0);
        b0 = __hfma2(bc2(UB.x), e[0], b0);
        a1 = __hfma2(bc2(UA.y), e[1], a1);
        b1 = __hfma2(bc2(UB.y), e[1], b1);
        a2 = __hfma2(bc2(UA.z), e[2], a2);
        b2 = __hfma2(bc2(UB.z), e[2], b2);
        a3 = __hfma2(bc2(UA.w), e[3], a3);
        b3 = __hfma2(bc2(UB.w), e[3], b3);
    }
    __nv_bfloat162 sa = __hadd2(__hadd2(a0, a1), __hadd2(a2, a3));
    __nv_bfloat162 sb = __hadd2(__hadd2(b0, b1), __hadd2(b2, b3));
    outA = __low2float(sa) + __high2float(sa);
    outB = __low2float(sb) + __high2float(sb);
}

__global__ __launch_bounds__(128, 2) void crf_main(
    const float *__restrict__ inputs,       // [B, L, T]
    const float *__restrict__ trans,        // [T, T]
    const float *__restrict__ start_t,      // [T]
    const float *__restrict__ end_t,        // [T]
    float *__restrict__ out)                // [1] (zeroed here)
{
    const int tid = threadIdx.x;
    const int lane = tid & 31;
    const int wid = tid >> 5;
    const int c = blockIdx.x;
    const int fwd = (c < 64);
    const int b0 = fwd ? c : c - 64;
    const int b1 = b0 + 64;

    if (c == 0 && tid == 0) out[0] = 0.f;   // combine atomicAdds later

    const float *eA = inputs + (size_t)b0 * (LL * TT);
    const float *eB = inputs + (size_t)b1 * (LL * TT);

    __shared__ __align__(16) __nv_bfloat16 uA_sh[2][TT], uB_sh[2][TT];
    __shared__ __align__(16) unsigned redA[4], redB[4];
    __shared__ float red_f[8];

    __nv_bfloat162 Ec[64];       // packed E column (fwd) / row (bwd), SHARED
    float rA[8], rB[8];          // emission LDG register rings (8 ahead)
    int ksA = 0, ksB = 0;
    float unA, unB;

    // ---- E into registers: column (fwd) / row (bwd), packed bf16x2 --------
    if (fwd) {
#pragma unroll
        for (int q = 0; q < 64; q++) {
            float lo = __expf(trans[(2 * q) * TT + tid]);
            float hi = __expf(trans[(2 * q + 1) * TT + tid]);
            Ec[q] = __floats2bfloat162_rn(lo, hi);
        }
    } else {
        const float2 *trow = (const float2 *)(trans + tid * TT);
#pragma unroll
        for (int q = 0; q < 64; q++) {
            float2 tv = trow[q];
            Ec[q] = __floats2bfloat162_rn(__expf(tv.x), __expf(tv.y));
        }
    }

    if (fwd) {
        // ========== FORWARD pair: a_0 .. a_511 for batches b0, b1 ==========
        float a0A = start_t[tid] + eA[tid];
        float a0B = start_t[tid] + eB[tid];
        float mvA = a0A, mvB = a0B;
#pragma unroll
        for (int o = 16; o; o >>= 1) {
            mvA = fmaxf(mvA, __shfl_xor_sync(0xffffffffu, mvA, o));
            mvB = fmaxf(mvB, __shfl_xor_sync(0xffffffffu, mvB, o));
        }
        if (lane == 0) { red_f[wid] = mvA; red_f[4 + wid] = mvB; }
        __syncthreads();
        const float mxA =
            fmaxf(fmaxf(red_f[0], red_f[1]), fmaxf(red_f[2], red_f[3]));
        const float mxB =
            fmaxf(fmaxf(red_f[4], red_f[5]), fmaxf(red_f[6], red_f[7]));
        unA = __expf(a0A - mxA);
        unB = __expf(a0B - mxB);
        uA_sh[0][tid] = __float2bfloat16(unA);
        uB_sh[0][tid] = __float2bfloat16(unB);
        {
            unsigned wa = __reduce_max_sync(0xffffffffu, __float_as_uint(unA));
            unsigned wb = __reduce_max_sync(0xffffffffu, __float_as_uint(unB));
            if (lane == 0) { redA[wid] = wa; redB[wid] = wb; }
        }
        if (tid == 0) { g_mx0[b0] = mxA; g_mx0[b1] = mxB; }
#pragma unroll
        for (int i = 0; i < 8; i++) {
            rA[i] = eA[(1 + i) * TT + tid];
            rB[i] = eB[(1 + i) * TT + tid];
        }
        __syncthreads();

        // 511 steps; step s consumes emission row s+1.
        // renorm: capture at s%8==7, apply at s%8==0 (init capture for s=0).
        auto fwd_step = [&](int s, int j) {
            float mA = __expf(rA[j]);
            float mB = __expf(rB[j]);
            int nrow = s + 9; if (nrow > HALF - 1) nrow = HALF - 1;
            const float nA = eA[nrow * TT + tid];
            const float nB = eB[nrow * TT + tid];
            if ((s & 7) == 0) {           // apply exact pow-2 scales
                uint4 qa = *(const uint4 *)redA;
                uint4 qb = *(const uint4 *)redB;
                unsigned ma = max(max(qa.x, qa.y), max(qa.z, qa.w));
                unsigned mb = max(max(qb.x, qb.y), max(qb.z, qb.w));
                int kA = (int)(ma >> 23) - 127;
                int kB = (int)(mb >> 23) - 127;
                ksA += kA; ksB += kB;
                mA *= __uint_as_float((unsigned)(127 - kA) << 23);
                mB *= __uint_as_float((unsigned)(127 - kB) << 23);
            }
            float sA, sB;
            matvec_bf16_dual(
                reinterpret_cast<const uint4 *>(uA_sh[s & 1]),
                reinterpret_cast<const uint4 *>(uB_sh[s & 1]), Ec, sA, sB);
            unA = sA * mA;
            unB = sB * mB;
            rA[j] = nA; rB[j] = nB;
            uA_sh[(s + 1) & 1][tid] = __float2bfloat16(unA);
            uB_sh[(s + 1) & 1][tid] = __float2bfloat16(unB);
            if ((s & 7) == 7) {
                unsigned wa = __reduce_max_sync(0xffffffffu, __float_as_uint(unA));
                unsigned wb = __reduce_max_sync(0xffffffffu, __float_as_uint(unB));
                if (lane == 0) { redA[wid] = wa; redB[wid] = wb; }
            }
            __syncthreads();
        };
#pragma unroll 1
        for (int blk = 0; blk < 63; ++blk) {
#pragma unroll
            for (int sub = 0; sub < 8; ++sub)
                fwd_step(blk * 8 + sub, sub);
        }
#pragma unroll
        for (int sub = 0; sub < 7; ++sub)     // tail: s = 504..510
            fwd_step(504 + sub, sub);

        g_alpha[b0][tid] = unA;
        g_alpha[b1][tid] = unB;
        if (tid == 0) { g_kf[b0] = ksA; g_kf[b1] = ksB; }
    } else {
        // ========== BACKWARD pair: beta_1024 -> beta_512 for b0, b1 ========
        unA = unB = __expf(end_t[tid]);    // same init, diverge at s=0
        {
            unsigned wa = __reduce_max_sync(0xffffffffu, __float_as_uint(unA));
            if (lane == 0) { redA[wid] = wa; redB[wid] = wa; }
        }
#pragma unroll
        for (int i = 0; i < 8; i++) {
            rA[i] = eA[(1023 - i) * TT + tid];
            rB[i] = eB[(1023 - i) * TT + tid];
        }
        __syncthreads();

        // 512 steps; step s consumes emission row 1023-s.
        // renorm: capture post-matvec at s%8==7, apply at s%8==1.
        auto bwd_step = [&](int s, int j) {
            float mA = __expf(rA[j]);
            float mB = __expf(rB[j]);
            float vA = unA * mA;
            float vB = unB * mB;
            if ((s & 7) == 1) {
                uint4 qa = *(const uint4 *)redA;
                uint4 qb = *(const uint4 *)redB;
                unsigned ma = max(max(qa.x, qa.y), max(qa.z, qa.w));
                unsigned mb = max(max(qb.x, qb.y), max(qb.z, qb.w));
                int kA = (int)(ma >> 23) - 127;
                int kB = (int)(mb >> 23) - 127;
                ksA += kA; ksB += kB;
                vA *= __uint_as_float((unsigned)(127 - kA) << 23);
                vB *= __uint_as_float((unsigned)(127 - kB) << 23);
            }
            uA_sh[s & 1][tid] = __float2bfloat16(vA);
            uB_sh[s & 1][tid] = __float2bfloat16(vB);
            __syncthreads();              // v published
            // post-barrier window: independent prefetch before dependent LDS
            int nrow = 1023 - s - 8; if (nrow < HALF) nrow = HALF;
            rA[j] = eA[nrow * TT + tid];
            rB[j] = eB[nrow * TT + tid];
            matvec_bf16_dual(
                reinterpret_cast<const uint4 *>(uA_sh[s & 1]),
                reinterpret_cast<const uint4 *>(uB_sh[s & 1]), Ec, unA, unB);
            if ((s & 7) == 7) {
                unsigned wa = __reduce_max_sync(0xffffffffu, __float_as_uint(unA));
                unsigned wb = __reduce_max_sync(0xffffffffu, __float_as_uint(unB));
                if (lane == 0) { redA[wid] = wa; redB[wid] = wb; }
            }
        };
#pragma unroll 1
        for (int blk = 0; blk < 64; ++blk) {
#pragma unroll
            for (int sub = 0; sub < 8; ++sub)
                bwd_step(blk * 8 + sub, sub);
        }

        g_beta[b0][tid] = unA;
        g_beta[b1][tid] = unB;
        if (tid == 0) { g_kb[b0] = ksA; g_kb[b1] = ksB; }
    }
}

// Per-batch: numerator gathers + alpha.beta dot + logs -> atomicAdd(out)
__global__ __launch_bounds__(128) void crf_combine(
    const float *__restrict__ inputs,
    const void *__restrict__ tags_raw,
    const float *__restrict__ trans,
    const float *__restrict__ start_t,
    const float *__restrict__ end_t,
    float *__restrict__ out)
{
    const int b = blockIdx.x;
    const int tid = threadIdx.x;
    const int lane = tid & 31;
    const int wid = tid >> 5;
    __shared__ float rf[8];

    const float *emitB = inputs + (size_t)b * (LL * TT);

    // tags dtype detection: probe batch-0 odd int32 words (always in-bounds).
    const int *t32 = (const int *)tags_raw;
    const int is64 = !__syncthreads_or(t32[2 * tid + 1] != 0);
    const long long *t64 = (const long long *)tags_raw;
    const long tb = (long)b * LL;
    auto tg = [&](int t) -> int {
        return is64 ? (int)t64[tb + t] : t32[tb + t];
    };

    // numerator
    float np = 0.f;
#pragma unroll
    for (int k = 0; k < 8; k++) {
        int t = tid + 128 * k;
        int g = tg(t);
        np += emitB[t * TT + g];
        if (t < LL - 1) np += trans[g * TT + tg(t + 1)];
    }
    if (tid == 0) np += start_t[tg(0)] + end_t[tg(LL - 1)];

    // alpha . beta
    float p = g_alpha[b][tid] * g_beta[b][tid];

#pragma unroll
    for (int o = 16; o; o >>= 1) {
        np += __shfl_xor_sync(0xffffffffu, np, o);
        p  += __shfl_xor_sync(0xffffffffu, p, o);
    }
    if (lane == 0) { rf[wid] = np; rf[4 + wid] = p; }
    __syncthreads();
    if (tid == 0) {
        float num = rf[0] + rf[1] + rf[2] + rf[3];
        float S = rf[4] + rf[5] + rf[6] + rf[7];
        double logZ = (double)g_mx0[b] +
                      (double)(g_kf[b] + g_kb[b]) * LN2 + log((double)S);
        atomicAdd(out, (float)((double)num - logZ));
    }
}

extern "C" void kernel_launch(void *const *d_in, const int *in_sizes, int n_in,
                              void *d_out, int out_size) {
    const float *inputs    = (const float *)d_in[0];
    const void  *tags      = (const void *)d_in[1];
    // d_in[2] = mask (all ones by construction) — unused
    const float *trans     = (const float *)d_in[3];
    const float *start_t   = (const float *)d_in[4];
    const float *end_t     = (const float *)d_in[5];
    float *out = (float *)d_out;

    crf_main<<<BB, 128>>>(inputs, trans, start_t, end_t, out);
    crf_combine<<<BB, 128>>>(inputs, tags, trans, start_t, end_t, out);
}